// round 15
// baseline (speedup 1.0000x reference)
#include <cuda_runtime.h>
#include <math.h>

#define Bq 4
#define Sq 4096
#define Hq 1024
#define NHq 16
#define Dq 64
#define Rq 2
#define SCALEq 0.125f

// scratch (no allocation allowed)
__device__ float g_cnt[Bq*Sq*2];         // [b][s] float2 (r0,r1)
__device__ float g_xsum[Bq*Rq*Hq];
__device__ float g_t[Bq*Hq];             // (xsum0-xsum1) @ Wk
__device__ float g_vsum[Bq*Rq*Hq];
__device__ float g_pdiff[Bq*NHq*Hq];
__device__ float g_bdiff[Bq*NHq];

// ================= k_hist: per-b histogram of both r + buffer init =================
__global__ void __launch_bounds__(512)
k_hist(const int* __restrict__ idx, const float* __restrict__ bv) {
    __shared__ int sh0[Sq];              // 16KB
    __shared__ int sh1[Sq];              // 16KB
    int b = blockIdx.x, tid = threadIdx.x;
    for (int j = tid; j < Sq; j += 512) { sh0[j] = 0; sh1[j] = 0; }
    for (int i = tid; i < Hq; i += 512) {
        g_xsum[(b*Rq + 0)*Hq + i] = 0.f;
        g_xsum[(b*Rq + 1)*Hq + i] = 0.f;
        g_t[b*Hq + i] = 0.f;
        float sv = 4096.f * bv[i];
        g_vsum[(b*Rq + 0)*Hq + i] = sv;
        g_vsum[(b*Rq + 1)*Hq + i] = sv;
    }
    __syncthreads();
    const int2* ip = (const int2*)(idx + (size_t)b * Sq * Rq);
    for (int s = tid; s < Sq; s += 512) {
        int2 p = ip[s];
        atomicAdd(&sh0[p.x], 1);
        atomicAdd(&sh1[p.y], 1);
    }
    __syncthreads();
    float2* c2 = (float2*)g_cnt + b*Sq;
    for (int j = tid; j < Sq; j += 512)
        c2[j] = make_float2((float)sh0[j], (float)sh1[j]);
}

// ================= k_xsum: front-batched 8-deep loads =================
#define SCHUNKS 128
#define SROWS (Sq / SCHUNKS)             // 32
__global__ void __launch_bounds__(256)
k_xsum(const float* __restrict__ x) {
    int b = blockIdx.y, tid = threadIdx.x;
    int s0 = blockIdx.x * SROWS;
    const float2* cnt2 = (const float2*)g_cnt + b*Sq;
    const float4* xb4 = (const float4*)(x + (size_t)b * Sq * Hq);
    float4 a0 = make_float4(0.f,0.f,0.f,0.f);
    float4 a1 = make_float4(0.f,0.f,0.f,0.f);
    #pragma unroll
    for (int g = 0; g < SROWS/8; g++) {
        int s = s0 + g*8;
        float4 xv[8];                    // 8 independent LDG.128 in flight
        #pragma unroll
        for (int k = 0; k < 8; k++) xv[k] = xb4[(size_t)(s + k) * 256 + tid];
        float2 c[8];
        #pragma unroll
        for (int k = 0; k < 8; k++) c[k] = cnt2[s + k];
        #pragma unroll
        for (int k = 0; k < 8; k++) {
            a0.x += c[k].x*xv[k].x; a0.y += c[k].x*xv[k].y;
            a0.z += c[k].x*xv[k].z; a0.w += c[k].x*xv[k].w;
            a1.x += c[k].y*xv[k].x; a1.y += c[k].y*xv[k].y;
            a1.z += c[k].y*xv[k].z; a1.w += c[k].y*xv[k].w;
        }
    }
    float* o0 = &g_xsum[(b*Rq + 0)*Hq + tid*4];
    float* o1 = &g_xsum[(b*Rq + 1)*Hq + tid*4];
    atomicAdd(o0+0, a0.x); atomicAdd(o0+1, a0.y); atomicAdd(o0+2, a0.z); atomicAdd(o0+3, a0.w);
    atomicAdd(o1+0, a1.x); atomicAdd(o1+1, a1.y); atomicAdd(o1+2, a1.z); atomicAdd(o1+3, a1.w);
}

// ================= k_proj: t = xd@Wk (y=0) ; vsum += xsum@Wv (y=1) =================
__global__ void __launch_bounds__(256)
k_proj(const float* __restrict__ Wk, const float* __restrict__ Wv) {
    __shared__ float xa[16][8];
    int tid = threadIdx.x;
    int hc = blockIdx.x * 16;
    if (blockIdx.y == 0) {
        if (tid < 64) {
            int hl = tid >> 2, b = tid & 3;
            xa[hl][b] = g_xsum[(b*Rq + 0)*Hq + hc + hl] - g_xsum[(b*Rq + 1)*Hq + hc + hl];
        }
        __syncthreads();
        float4 acc[4];
        #pragma unroll
        for (int b = 0; b < 4; b++) acc[b] = make_float4(0.f,0.f,0.f,0.f);
        const float4* W4 = (const float4*)Wk;
        #pragma unroll
        for (int hl = 0; hl < 16; hl++) {
            float4 w = W4[(size_t)(hc + hl) * 256 + tid];
            #pragma unroll
            for (int b = 0; b < 4; b++) {
                float xv = xa[hl][b];
                acc[b].x += xv*w.x; acc[b].y += xv*w.y; acc[b].z += xv*w.z; acc[b].w += xv*w.w;
            }
        }
        #pragma unroll
        for (int b = 0; b < 4; b++) {
            float* o = &g_t[b*Hq + tid*4];
            atomicAdd(o+0, acc[b].x); atomicAdd(o+1, acc[b].y);
            atomicAdd(o+2, acc[b].z); atomicAdd(o+3, acc[b].w);
        }
    } else {
        if (tid < 128) {
            int hl = tid >> 3, br = tid & 7;
            xa[hl][br] = g_xsum[br*Hq + hc + hl];
        }
        __syncthreads();
        float4 acc[8];
        #pragma unroll
        for (int br = 0; br < 8; br++) acc[br] = make_float4(0.f,0.f,0.f,0.f);
        const float4* W4 = (const float4*)Wv;
        #pragma unroll
        for (int hl = 0; hl < 16; hl++) {
            float4 w = W4[(size_t)(hc + hl) * 256 + tid];
            #pragma unroll
            for (int br = 0; br < 8; br++) {
                float xv = xa[hl][br];
                acc[br].x += xv*w.x; acc[br].y += xv*w.y; acc[br].z += xv*w.z; acc[br].w += xv*w.w;
            }
        }
        #pragma unroll
        for (int br = 0; br < 8; br++) {
            float* o = &g_vsum[br*Hq + tid*4];
            atomicAdd(o+0, acc[br].x); atomicAdd(o+1, acc[br].y);
            atomicAdd(o+2, acc[br].z); atomicAdd(o+3, acc[br].w);
        }
    }
}

// ================= k_pdiff: warp-per-Wq-row, front-batched loads =================
__global__ void __launch_bounds__(256)
k_pdiff(const float* __restrict__ Wq, const float* __restrict__ bq) {
    __shared__ float st[Bq*Hq];          // t staged, 16KB
    int tid = threadIdx.x;
    for (int i = tid; i < Bq*Hq; i += 256) st[i] = g_t[i];
    __syncthreads();

    int warp = tid >> 5, lane = tid & 31;
    int wg = blockIdx.x * 8 + warp;

    if (wg < 1024) {
        int h = wg;
        const float4* wr = (const float4*)(Wq + (size_t)h * Hq);
        float4 w[8];
        #pragma unroll
        for (int j = 0; j < 8; j++) w[j] = wr[j*32 + lane];

        float acc[Bq][8];
        #pragma unroll
        for (int b = 0; b < Bq; b++) {
            const float4* tb = (const float4*)&st[b*Hq];
            #pragma unroll
            for (int j = 0; j < 8; j++) {
                float4 tv = tb[j*32 + lane];     // head n = 2j + (lane>>4)
                acc[b][j] = w[j].x*tv.x + w[j].y*tv.y + w[j].z*tv.z + w[j].w*tv.w;
            }
        }
        #pragma unroll
        for (int b = 0; b < Bq; b++)
            #pragma unroll
            for (int j = 0; j < 8; j++) {
                float v = acc[b][j];
                v += __shfl_xor_sync(0xffffffffu, v, 8);
                v += __shfl_xor_sync(0xffffffffu, v, 4);
                v += __shfl_xor_sync(0xffffffffu, v, 2);
                v += __shfl_xor_sync(0xffffffffu, v, 1);
                acc[b][j] = v;
            }
        if ((lane & 15) == 0) {
            int half = lane >> 4;
            #pragma unroll
            for (int b = 0; b < Bq; b++)
                #pragma unroll
                for (int j = 0; j < 8; j++)
                    g_pdiff[(b*NHq + (2*j + half))*Hq + h] = SCALEq * acc[b][j];
        }
    } else if (wg < 1024 + Bq*NHq) {
        int id = wg - 1024;
        int b = id >> 4, n = id & 15;
        float s = bq[n*Dq + lane]      * st[b*Hq + n*Dq + lane]
                + bq[n*Dq + 32 + lane] * st[b*Hq + n*Dq + 32 + lane];
        #pragma unroll
        for (int o = 16; o > 0; o >>= 1) s += __shfl_xor_sync(0xffffffffu, s, o);
        if (lane == 0) g_bdiff[b*NHq + n] = SCALEq * s;
    }
}

// ================= k_main: 224 thr (reg cap 146) -> 2-deep prefetch, 4 rows/warp =================
#define MTHR 224
#define MROWS 28                          // 7 warps * 4 rows
#define MBLKS ((Sq + MROWS - 1) / MROWS)  // 147
#define SMEM_MAIN ((NHq*Hq + 2*Hq + 16) * sizeof(float))
__global__ void __launch_bounds__(MTHR, 2)
k_main(const float* __restrict__ x, float* __restrict__ out) {
    extern __shared__ float sm[];
    float* sPd = sm;                 // [16][1024]
    float* sV0 = sm + NHq*Hq;        // [1024]
    float* sV1 = sV0 + Hq;           // [1024]
    float* sBd = sV1 + Hq;           // [16]

    int b = blockIdx.y, tid = threadIdx.x;
    {
        const float4* gp4 = (const float4*)&g_pdiff[b*NHq*Hq];
        float4* sp4 = (float4*)sPd;
        for (int i = tid; i < NHq*Hq/4; i += MTHR) sp4[i] = gp4[i];
        const float4* v0g = (const float4*)&g_vsum[(b*Rq + 0)*Hq];
        const float4* v1g = (const float4*)&g_vsum[(b*Rq + 1)*Hq];
        float4* s04 = (float4*)sV0; float4* s14 = (float4*)sV1;
        for (int i = tid; i < Hq/4; i += MTHR) { s04[i] = v0g[i]; s14[i] = v1g[i]; }
        if (tid < NHq) sBd[tid] = g_bdiff[b*NHq + tid];
    }
    __syncthreads();

    int warp = tid >> 5, lane = tid & 31;
    int r0 = blockIdx.x * MROWS + warp * 4;
    if (r0 >= Sq) return;                          // tail guard (no later __syncthreads)
    const float* xb = x + (size_t)b * Sq * Hq;
    float* ob = out + (size_t)b * Sq * Hq;

    const float4* xr4[4];
    #pragma unroll
    for (int i = 0; i < 4; i++)
        xr4[i] = (const float4*)(xb + (size_t)(r0 + i) * Hq);
    const float4* sPd4 = (const float4*)sPd;

    float acc[4][NHq];
    #pragma unroll
    for (int i = 0; i < 4; i++)
        #pragma unroll
        for (int n = 0; n < NHq; n++) acc[i][n] = 0.f;

    // 2-deep rotating prefetch: while computing step j, loads for j+1 AND j+2 are in flight
    float4 bufA[4], bufB[4], bufC[4];
    #pragma unroll
    for (int i = 0; i < 4; i++) bufA[i] = xr4[i][lane];
    #pragma unroll
    for (int i = 0; i < 4; i++) bufB[i] = xr4[i][lane + 32];

    #pragma unroll
    for (int j = 0; j < 8; j++) {               // 8 * 32 lanes * float4 = 1024 h
        int h4 = lane + 32*j;
        if (j < 6) {
            #pragma unroll
            for (int i = 0; i < 4; i++) bufC[i] = xr4[i][h4 + 64];
        }
        #pragma unroll
        for (int n = 0; n < NHq; n++) {
            float4 pd = sPd4[n*256 + h4];
            #pragma unroll
            for (int i = 0; i < 4; i++) {
                acc[i][n] += bufA[i].x*pd.x + bufA[i].y*pd.y + bufA[i].z*pd.z + bufA[i].w*pd.w;
            }
        }
        #pragma unroll
        for (int i = 0; i < 4; i++) { bufA[i] = bufB[i]; bufB[i] = bufC[i]; }
    }

    // warp-reduce all 64 partials (butterfly -> every lane has full sums)
    #pragma unroll
    for (int i = 0; i < 4; i++)
        #pragma unroll
        for (int n = 0; n < NHq; n++) {
            float v = acc[i][n];
            v += __shfl_xor_sync(0xffffffffu, v, 16);
            v += __shfl_xor_sync(0xffffffffu, v, 8);
            v += __shfl_xor_sync(0xffffffffu, v, 4);
            v += __shfl_xor_sync(0xffffffffu, v, 2);
            v += __shfl_xor_sync(0xffffffffu, v, 1);
            acc[i][n] = 1.f / (1.f + __expf(-(v + sBd[n])));   // prob for y=0
        }

    const float4* v04 = (const float4*)sV0;
    const float4* v14 = (const float4*)sV1;
    #pragma unroll
    for (int i = 0; i < 4; i++) {
        float4* o4 = (float4*)(ob + (size_t)(r0 + i) * Hq);
        #pragma unroll
        for (int j = 0; j < 8; j++) {
            int h4 = lane + 32*j;                  // float4 index; head = h4>>4
            float ppA = acc[i][2*j];               // lane < 16 half
            float ppB = acc[i][2*j + 1];           // lane >= 16 half
            float pp = (lane & 16) ? ppB : ppA;
            float4 a = v04[h4];
            float4 c = v14[h4];
            float4 o;
            o.x = c.x + pp * (a.x - c.x);
            o.y = c.y + pp * (a.y - c.y);
            o.z = c.z + pp * (a.z - c.z);
            o.w = c.w + pp * (a.w - c.w);
            __stcs(o4 + h4, o);                    // streaming store: keep x resident in L2
        }
    }
}

extern "C" void kernel_launch(void* const* d_in, const int* in_sizes, int n_in,
                              void* d_out, int out_size) {
    const float* x  = (const float*)d_in[0];
    // d_in[1] attention_mask: unused by reference
    const float* Wq = (const float*)d_in[2];
    const float* bq = (const float*)d_in[3];
    const float* Wk = (const float*)d_in[4];
    // d_in[5] bk cancels in the score difference
    const float* Wv = (const float*)d_in[6];
    const float* bv = (const float*)d_in[7];
    const int* idx  = (const int*)d_in[8];
    float* out = (float*)d_out;

    cudaFuncSetAttribute(k_main, cudaFuncAttributeMaxDynamicSharedMemorySize, (int)SMEM_MAIN);

    k_hist<<<Bq, 512>>>(idx, bv);
    k_xsum<<<dim3(SCHUNKS, Bq), 256>>>(x);
    k_proj<<<dim3(64, 2), 256>>>(Wk, Wv);
    k_pdiff<<<136, 256>>>(Wq, bq);
    k_main<<<dim3(MBLKS, Bq), MTHR, SMEM_MAIN>>>(x, out);
}

// round 17
// speedup vs baseline: 1.0045x; 1.0045x over previous
#include <cuda_runtime.h>
#include <math.h>

#define Bq 4
#define Sq 4096
#define Hq 1024
#define NHq 16
#define Dq 64
#define Rq 2
#define SCALEq 0.125f

typedef unsigned long long ull;
typedef unsigned int uint;

// scratch (no allocation allowed)
__device__ float g_cnt[Bq*Sq*2];         // [b][s] float2 (r0,r1)
__device__ float g_xsum[Bq*Rq*Hq];
__device__ float g_t[Bq*Hq];             // (xsum0-xsum1) @ Wk
__device__ float g_vsum[Bq*Rq*Hq];
__device__ float g_pdiff[Bq*NHq*Hq];
__device__ float g_bdiff[Bq*NHq];

// ---- packed f32x2 helpers ----
__device__ __forceinline__ ull pk(float lo, float hi) {
    ull r; asm("mov.b64 %0, {%1, %2};" : "=l"(r) : "f"(lo), "f"(hi)); return r;
}
__device__ __forceinline__ void fma2(ull& a, ull x, ull y) {
    asm("fma.rn.f32x2 %0, %1, %2, %0;" : "+l"(a) : "l"(x), "l"(y));
}
__device__ __forceinline__ ull add2(ull a, ull b) {
    ull r; asm("add.rn.f32x2 %0, %1, %2;" : "=l"(r) : "l"(a), "l"(b)); return r;
}
__device__ __forceinline__ ull shfl2x(ull v, int m) {
    uint lo = (uint)v, hi = (uint)(v >> 32);
    lo = __shfl_xor_sync(0xffffffffu, lo, m);
    hi = __shfl_xor_sync(0xffffffffu, hi, m);
    return ((ull)hi << 32) | (ull)lo;
}
__device__ __forceinline__ float ull_lo(ull v) { return __uint_as_float((uint)v); }
__device__ __forceinline__ float ull_hi(ull v) { return __uint_as_float((uint)(v >> 32)); }

// ================= k_hist: per-b histogram of both r + buffer init =================
__global__ void __launch_bounds__(512)
k_hist(const int* __restrict__ idx, const float* __restrict__ bv) {
    __shared__ int sh0[Sq];              // 16KB
    __shared__ int sh1[Sq];              // 16KB
    int b = blockIdx.x, tid = threadIdx.x;
    for (int j = tid; j < Sq; j += 512) { sh0[j] = 0; sh1[j] = 0; }
    for (int i = tid; i < Hq; i += 512) {
        g_xsum[(b*Rq + 0)*Hq + i] = 0.f;
        g_xsum[(b*Rq + 1)*Hq + i] = 0.f;
        g_t[b*Hq + i] = 0.f;
        float sv = 4096.f * bv[i];
        g_vsum[(b*Rq + 0)*Hq + i] = sv;
        g_vsum[(b*Rq + 1)*Hq + i] = sv;
    }
    __syncthreads();
    const int2* ip = (const int2*)(idx + (size_t)b * Sq * Rq);
    for (int s = tid; s < Sq; s += 512) {
        int2 p = ip[s];
        atomicAdd(&sh0[p.x], 1);
        atomicAdd(&sh1[p.y], 1);
    }
    __syncthreads();
    float2* c2 = (float2*)g_cnt + b*Sq;
    for (int j = tid; j < Sq; j += 512)
        c2[j] = make_float2((float)sh0[j], (float)sh1[j]);
}

// ================= k_xsum: front-batched 8-deep loads =================
#define SCHUNKS 128
#define SROWS (Sq / SCHUNKS)             // 32
__global__ void __launch_bounds__(256)
k_xsum(const float* __restrict__ x) {
    int b = blockIdx.y, tid = threadIdx.x;
    int s0 = blockIdx.x * SROWS;
    const float2* cnt2 = (const float2*)g_cnt + b*Sq;
    const float4* xb4 = (const float4*)(x + (size_t)b * Sq * Hq);
    float4 a0 = make_float4(0.f,0.f,0.f,0.f);
    float4 a1 = make_float4(0.f,0.f,0.f,0.f);
    #pragma unroll
    for (int g = 0; g < SROWS/8; g++) {
        int s = s0 + g*8;
        float4 xv[8];                    // 8 independent LDG.128 in flight
        #pragma unroll
        for (int k = 0; k < 8; k++) xv[k] = xb4[(size_t)(s + k) * 256 + tid];
        float2 c[8];
        #pragma unroll
        for (int k = 0; k < 8; k++) c[k] = cnt2[s + k];
        #pragma unroll
        for (int k = 0; k < 8; k++) {
            a0.x += c[k].x*xv[k].x; a0.y += c[k].x*xv[k].y;
            a0.z += c[k].x*xv[k].z; a0.w += c[k].x*xv[k].w;
            a1.x += c[k].y*xv[k].x; a1.y += c[k].y*xv[k].y;
            a1.z += c[k].y*xv[k].z; a1.w += c[k].y*xv[k].w;
        }
    }
    float* o0 = &g_xsum[(b*Rq + 0)*Hq + tid*4];
    float* o1 = &g_xsum[(b*Rq + 1)*Hq + tid*4];
    atomicAdd(o0+0, a0.x); atomicAdd(o0+1, a0.y); atomicAdd(o0+2, a0.z); atomicAdd(o0+3, a0.w);
    atomicAdd(o1+0, a1.x); atomicAdd(o1+1, a1.y); atomicAdd(o1+2, a1.z); atomicAdd(o1+3, a1.w);
}

// ================= k_proj: t = xd@Wk (y=0) ; vsum += xsum@Wv (y=1) =================
__global__ void __launch_bounds__(256)
k_proj(const float* __restrict__ Wk, const float* __restrict__ Wv) {
    __shared__ float xa[16][8];
    int tid = threadIdx.x;
    int hc = blockIdx.x * 16;
    if (blockIdx.y == 0) {
        if (tid < 64) {
            int hl = tid >> 2, b = tid & 3;
            xa[hl][b] = g_xsum[(b*Rq + 0)*Hq + hc + hl] - g_xsum[(b*Rq + 1)*Hq + hc + hl];
        }
        __syncthreads();
        float4 acc[4];
        #pragma unroll
        for (int b = 0; b < 4; b++) acc[b] = make_float4(0.f,0.f,0.f,0.f);
        const float4* W4 = (const float4*)Wk;
        #pragma unroll
        for (int hl = 0; hl < 16; hl++) {
            float4 w = W4[(size_t)(hc + hl) * 256 + tid];
            #pragma unroll
            for (int b = 0; b < 4; b++) {
                float xv = xa[hl][b];
                acc[b].x += xv*w.x; acc[b].y += xv*w.y; acc[b].z += xv*w.z; acc[b].w += xv*w.w;
            }
        }
        #pragma unroll
        for (int b = 0; b < 4; b++) {
            float* o = &g_t[b*Hq + tid*4];
            atomicAdd(o+0, acc[b].x); atomicAdd(o+1, acc[b].y);
            atomicAdd(o+2, acc[b].z); atomicAdd(o+3, acc[b].w);
        }
    } else {
        if (tid < 128) {
            int hl = tid >> 3, br = tid & 7;
            xa[hl][br] = g_xsum[br*Hq + hc + hl];
        }
        __syncthreads();
        float4 acc[8];
        #pragma unroll
        for (int br = 0; br < 8; br++) acc[br] = make_float4(0.f,0.f,0.f,0.f);
        const float4* W4 = (const float4*)Wv;
        #pragma unroll
        for (int hl = 0; hl < 16; hl++) {
            float4 w = W4[(size_t)(hc + hl) * 256 + tid];
            #pragma unroll
            for (int br = 0; br < 8; br++) {
                float xv = xa[hl][br];
                acc[br].x += xv*w.x; acc[br].y += xv*w.y; acc[br].z += xv*w.z; acc[br].w += xv*w.w;
            }
        }
        #pragma unroll
        for (int br = 0; br < 8; br++) {
            float* o = &g_vsum[br*Hq + tid*4];
            atomicAdd(o+0, acc[br].x); atomicAdd(o+1, acc[br].y);
            atomicAdd(o+2, acc[br].z); atomicAdd(o+3, acc[br].w);
        }
    }
}

// ================= k_pdiff: warp-per-Wq-row, front-batched loads =================
__global__ void __launch_bounds__(256)
k_pdiff(const float* __restrict__ Wq, const float* __restrict__ bq) {
    __shared__ float st[Bq*Hq];          // t staged, 16KB
    int tid = threadIdx.x;
    for (int i = tid; i < Bq*Hq; i += 256) st[i] = g_t[i];
    __syncthreads();

    int warp = tid >> 5, lane = tid & 31;
    int wg = blockIdx.x * 8 + warp;

    if (wg < 1024) {
        int h = wg;
        const float4* wr = (const float4*)(Wq + (size_t)h * Hq);
        float4 w[8];
        #pragma unroll
        for (int j = 0; j < 8; j++) w[j] = wr[j*32 + lane];

        float acc[Bq][8];
        #pragma unroll
        for (int b = 0; b < Bq; b++) {
            const float4* tb = (const float4*)&st[b*Hq];
            #pragma unroll
            for (int j = 0; j < 8; j++) {
                float4 tv = tb[j*32 + lane];     // head n = 2j + (lane>>4)
                acc[b][j] = w[j].x*tv.x + w[j].y*tv.y + w[j].z*tv.z + w[j].w*tv.w;
            }
        }
        #pragma unroll
        for (int b = 0; b < Bq; b++)
            #pragma unroll
            for (int j = 0; j < 8; j++) {
                float v = acc[b][j];
                v += __shfl_xor_sync(0xffffffffu, v, 8);
                v += __shfl_xor_sync(0xffffffffu, v, 4);
                v += __shfl_xor_sync(0xffffffffu, v, 2);
                v += __shfl_xor_sync(0xffffffffu, v, 1);
                acc[b][j] = v;
            }
        if ((lane & 15) == 0) {
            int half = lane >> 4;
            #pragma unroll
            for (int b = 0; b < Bq; b++)
                #pragma unroll
                for (int j = 0; j < 8; j++)
                    g_pdiff[(b*NHq + (2*j + half))*Hq + h] = SCALEq * acc[b][j];
        }
    } else if (wg < 1024 + Bq*NHq) {
        int id = wg - 1024;
        int b = id >> 4, n = id & 15;
        float s = bq[n*Dq + lane]      * st[b*Hq + n*Dq + lane]
                + bq[n*Dq + 32 + lane] * st[b*Hq + n*Dq + 32 + lane];
        #pragma unroll
        for (int o = 16; o > 0; o >>= 1) s += __shfl_xor_sync(0xffffffffu, s, o);
        if (lane == 0) g_bdiff[b*NHq + n] = SCALEq * s;
    }
}

// ================= k_main: f32x2 HEAD-pair packing (pd pre-interleaved in smem) =================
// acc[row][np] = f32x2 with lo = score head 2np, hi = score head 2np+1
#define SMEM_MAIN ((2*NHq*Hq/2*4 /*sPdP 64KB*/ + 2*Hq*4 + 64))
__global__ void __launch_bounds__(256, 2)
k_main(const float* __restrict__ x, float* __restrict__ out) {
    extern __shared__ float sm[];
    ull*   sPdP = (ull*)sm;          // [8][1024] interleaved head-pairs, 64KB
    float* sV0  = sm + 16384;        // [1024]
    float* sV1  = sV0 + Hq;          // [1024]
    float* sBd  = sV1 + Hq;          // [16]

    int b = blockIdx.y, tid = threadIdx.x;
    {
        // stage pdiff interleaved: sPdP[np*1024 + h] = (pd[2np][h], pd[2np+1][h])
        const float* gp = &g_pdiff[b*NHq*Hq];
        for (int i = tid; i < 8*Hq; i += 256) {
            int np = i >> 10, h = i & (Hq-1);
            sPdP[i] = pk(gp[(2*np)*Hq + h], gp[(2*np+1)*Hq + h]);
        }
        const float4* v0g = (const float4*)&g_vsum[(b*Rq + 0)*Hq];
        const float4* v1g = (const float4*)&g_vsum[(b*Rq + 1)*Hq];
        float4* s04 = (float4*)sV0; float4* s14 = (float4*)sV1;
        for (int i = tid; i < Hq/4; i += 256) { s04[i] = v0g[i]; s14[i] = v1g[i]; }
        if (tid < NHq) sBd[tid] = g_bdiff[b*NHq + tid];
    }
    __syncthreads();

    int warp = tid >> 5, lane = tid & 31, half = lane >> 4;
    int r0 = blockIdx.x * 32 + warp * 4;           // 8 warps * 4 rows = 32 rows/block
    const float* xb = x + (size_t)b * Sq * Hq;
    float* ob = out + (size_t)b * Sq * Hq;

    const float4* xr4[4];
    #pragma unroll
    for (int i = 0; i < 4; i++)
        xr4[i] = (const float4*)(xb + (size_t)(r0 + i) * Hq);   // row = 256 float4
    const ulonglong2* pp2 = (const ulonglong2*)sPdP;            // [np*512 + 2*h4 (+1)]

    ull acc[4][8];
    #pragma unroll
    for (int i = 0; i < 4; i++)
        #pragma unroll
        for (int np = 0; np < 8; np++) acc[i][np] = 0ull;

    float4 cur[4], nxt[4];
    #pragma unroll
    for (int i = 0; i < 4; i++) cur[i] = xr4[i][lane];

    #pragma unroll
    for (int j = 0; j < 8; j++) {               // 8 * 32 lanes * float4 = 1024 h
        int h4 = lane + 32*j;
        if (j < 7) {
            #pragma unroll
            for (int i = 0; i < 4; i++) nxt[i] = xr4[i][h4 + 32];
        }
        // broadcast each x component into both f32x2 halves (no cross-row packing)
        ull xp[4][4];
        #pragma unroll
        for (int i = 0; i < 4; i++) {
            xp[i][0] = pk(cur[i].x, cur[i].x);
            xp[i][1] = pk(cur[i].y, cur[i].y);
            xp[i][2] = pk(cur[i].z, cur[i].z);
            xp[i][3] = pk(cur[i].w, cur[i].w);
        }
        #pragma unroll
        for (int np = 0; np < 8; np++) {
            ulonglong2 pdA = pp2[np*512 + 2*h4];       // head-pair values for h = 4*h4, 4*h4+1
            ulonglong2 pdB = pp2[np*512 + 2*h4 + 1];   // h = 4*h4+2, 4*h4+3
            #pragma unroll
            for (int i = 0; i < 4; i++) {
                fma2(acc[i][np], xp[i][0], pdA.x);
                fma2(acc[i][np], xp[i][1], pdA.y);
                fma2(acc[i][np], xp[i][2], pdB.x);
                fma2(acc[i][np], xp[i][3], pdB.y);
            }
        }
        #pragma unroll
        for (int i = 0; i < 4; i++) cur[i] = nxt[i];
    }

    // packed butterfly reduction (each ull holds heads 2np|2np+1 partial sums)
    #pragma unroll
    for (int i = 0; i < 4; i++)
        #pragma unroll
        for (int np = 0; np < 8; np++) {
            ull v = acc[i][np];
            v = add2(v, shfl2x(v, 16));
            v = add2(v, shfl2x(v, 8));
            v = add2(v, shfl2x(v, 4));
            v = add2(v, shfl2x(v, 2));
            v = add2(v, shfl2x(v, 1));
            acc[i][np] = v;
        }

    float bdl[8];
    #pragma unroll
    for (int j = 0; j < 8; j++) bdl[j] = sBd[2*j + half];

    const float4* v04 = (const float4*)sV0;
    const float4* v14 = (const float4*)sV1;
    #pragma unroll
    for (int i = 0; i < 4; i++) {
        float4* o4 = (float4*)(ob + (size_t)(r0 + i) * Hq);
        #pragma unroll
        for (int j = 0; j < 8; j++) {
            int h4 = lane + 32*j;                  // head n = h4>>4 = 2j + half -> pair j, parity half
            ull v = acc[i][j];
            float s = half ? ull_hi(v) : ull_lo(v);
            float pp = 1.f / (1.f + __expf(-(s + bdl[j])));
            float4 a = v04[h4];
            float4 c = v14[h4];
            float4 o;
            o.x = c.x + pp * (a.x - c.x);
            o.y = c.y + pp * (a.y - c.y);
            o.z = c.z + pp * (a.z - c.z);
            o.w = c.w + pp * (a.w - c.w);
            __stcs(o4 + h4, o);                    // streaming store: keep x resident in L2
        }
    }
}

extern "C" void kernel_launch(void* const* d_in, const int* in_sizes, int n_in,
                              void* d_out, int out_size) {
    const float* x  = (const float*)d_in[0];
    // d_in[1] attention_mask: unused by reference
    const float* Wq = (const float*)d_in[2];
    const float* bq = (const float*)d_in[3];
    const float* Wk = (const float*)d_in[4];
    // d_in[5] bk cancels in the score difference
    const float* Wv = (const float*)d_in[6];
    const float* bv = (const float*)d_in[7];
    const int* idx  = (const int*)d_in[8];
    float* out = (float*)d_out;

    cudaFuncSetAttribute(k_main, cudaFuncAttributeMaxDynamicSharedMemorySize, (int)SMEM_MAIN);

    k_hist<<<Bq, 512>>>(idx, bv);
    k_xsum<<<dim3(SCHUNKS, Bq), 256>>>(x);
    k_proj<<<dim3(64, 2), 256>>>(Wk, Wv);
    k_pdiff<<<136, 256>>>(Wq, bq);
    k_main<<<dim3(Sq/32, Bq), 256, SMEM_MAIN>>>(x, out);
}